// round 7
// baseline (speedup 1.0000x reference)
#include <cuda_runtime.h>
#include <cuda_bf16.h>
#include <cstdint>

// ---------------------------------------------------------------------------
// SudokuPasses: 4 passes of {filter(box), pointing(h), pointing(v),
// unique(h), unique(v), unique(box), doubles(v), doubles(v), doubles(box)}
// over B=32768 puzzles of (9 digits, 9 rows, 9 cols) {0,1} float masks.
//
// pack floats -> 81 x 9-bit cell masks, solve in registers (1 thread/puzzle),
// unpack to float.
// R6: solver grid rebalanced to 1 CTA/SM (224 thr, contiguous chunks) so the
//     busiest SM does 224 puzzles instead of 256; doubles pd derived from
//     flag after the pair loop (9 predicated ORs instead of 36).
// ---------------------------------------------------------------------------

#define MAX_B 32768
#define CELLS 81
#define SOLVE_TPB 224   // 7 warps; 147 blocks -> exactly one CTA per SM

__device__ unsigned int g_pack[MAX_B * CELLS];

// ---------------------------------------------------------------------------
__global__ void pack_kernel(const float* __restrict__ in, int B)
{
    int idx = blockIdx.x * blockDim.x + threadIdx.x;
    if (idx >= B * CELLS) return;
    int b    = idx / CELLS;
    int cell = idx % CELLS;
    const float* p = in + (size_t)b * 729 + cell;
    unsigned m = 0;
#pragma unroll
    for (int d = 0; d < 9; ++d) {
        m |= (__ldcs(p + d * 81) != 0.0f) ? (1u << d) : 0u;
    }
    g_pack[idx] = m;
}

// ---------------------------------------------------------------------------
__global__ void unpack_kernel(float* __restrict__ out, int B)
{
    int idx = blockIdx.x * blockDim.x + threadIdx.x;
    if (idx >= B * 729) return;
    int b    = idx / 729;
    int r3   = idx % 729;
    int d    = r3 / 81;
    int cell = r3 % 81;
    unsigned m = g_pack[b * CELLS + cell];
    __stcs(out + idx, (float)((m >> d) & 1u));
}

// ---------------------------------------------------------------------------
#define ROW_IDX(l, k)  ((l) * 9 + (k))
#define COL_IDX(l, k)  ((k) * 9 + (l))
#define BOX_IDX(l, k)  ((((l) / 3) * 3 + ((k) / 3)) * 9 + ((l) % 3) * 3 + ((k) % 3))

// Hidden single: per-digit-bit count across the 9 cells of a line.
// count==1  <=>  parity set AND no carry ever generated.
#define UNIQUE_LINE(IDX)                                                      \
    _Pragma("unroll")                                                         \
    for (int l = 0; l < 9; ++l) {                                             \
        unsigned ones = 0, more = 0;                                          \
        _Pragma("unroll")                                                     \
        for (int k = 0; k < 9; ++k) {                                         \
            unsigned x = m[IDX(l, k)];                                        \
            more |= ones & x;                                                 \
            ones ^= x;                                                        \
        }                                                                     \
        unsigned e1 = ones & ~more;                                           \
        _Pragma("unroll")                                                     \
        for (int k = 0; k < 9; ++k) {                                         \
            unsigned v = m[IDX(l, k)];                                        \
            unsigned h = v & e1;                                              \
            m[IDX(l, k)] = h ? h : v;                                         \
        }                                                                     \
    }

// Naked pair: dot==2 between 2-candidate cells <=> identical patterns.
// Pair cells keep their mask; everyone else loses the pair digits.
// pd (union of pair digits) derived from flagged cells after the pair loop.
#define DOUBLES_LINE(IDX)                                                     \
    _Pragma("unroll")                                                         \
    for (int l = 0; l < 9; ++l) {                                             \
        unsigned v[9], pm[9];                                                 \
        _Pragma("unroll")                                                     \
        for (int k = 0; k < 9; ++k) {                                         \
            v[k]  = m[IDX(l, k)];                                             \
            pm[k] = (__popc(v[k]) == 2) ? v[k] : 0u;                          \
        }                                                                     \
        unsigned flag = 0;                                                    \
        _Pragma("unroll")                                                     \
        for (int c = 0; c < 9; ++c) {                                         \
            if (pm[c] != 0u) {                                                \
                _Pragma("unroll")                                             \
                for (int e = c + 1; e < 9; ++e) {                             \
                    if (pm[c] == pm[e]) {                                     \
                        flag |= (1u << c) | (1u << e);                        \
                    }                                                         \
                }                                                             \
            }                                                                 \
        }                                                                     \
        unsigned pd = 0;                                                      \
        _Pragma("unroll")                                                     \
        for (int k = 0; k < 9; ++k) {                                         \
            if (flag & (1u << k)) pd |= pm[k];                                \
        }                                                                     \
        unsigned npd = ~pd;                                                   \
        _Pragma("unroll")                                                     \
        for (int k = 0; k < 9; ++k) {                                         \
            m[IDX(l, k)] = (flag & (1u << k)) ? v[k] : (v[k] & npd);          \
        }                                                                     \
    }

__global__ void __launch_bounds__(SOLVE_TPB)
solve_kernel(float* __restrict__ out_tail, int B, int tail_mode)
{
    int b = blockIdx.x * SOLVE_TPB + threadIdx.x;
    if (b >= B) return;

    unsigned m[CELLS];
#pragma unroll
    for (int i = 0; i < CELLS; ++i) m[i] = g_pack[b * CELLS + i];

#pragma unroll 1
    for (int pass = 0; pass < 4; ++pass) {
        // ---- 1. filter box: solved cell's digit removed from rest of box;
        //         a digit solved twice in a box eliminates both.
#pragma unroll
        for (int bx = 0; bx < 9; ++bx) {
            const int base = (bx / 3) * 27 + (bx % 3) * 3;
            unsigned s[9], seen = 0, seen2 = 0;
#pragma unroll
            for (int k = 0; k < 9; ++k) {
                int idx = base + (k / 3) * 9 + (k % 3);
                unsigned vv = m[idx];
                unsigned sv = (__popc(vv) == 1) ? vv : 0u;
                s[k] = sv;
                seen2 |= seen & sv;
                seen  |= sv;
            }
#pragma unroll
            for (int k = 0; k < 9; ++k) {
                int idx = base + (k / 3) * 9 + (k % 3);
                unsigned other = (seen & ~s[k]) | (seen2 & s[k]);
                m[idx] &= ~other;
            }
        }

        // ---- 2. pointing h
#pragma unroll
        for (int br = 0; br < 3; ++br) {
            unsigned seg[3][3];   // [ri][bc]
#pragma unroll
            for (int ri = 0; ri < 3; ++ri)
#pragma unroll
                for (int bc = 0; bc < 3; ++bc) {
                    int c0 = (3 * br + ri) * 9 + 3 * bc;
                    seg[ri][bc] = m[c0] | m[c0 + 1] | m[c0 + 2];
                }
            unsigned p[3][3];
#pragma unroll
            for (int bc = 0; bc < 3; ++bc) {
                unsigned a = seg[0][bc], bb = seg[1][bc], cc = seg[2][bc];
                unsigned e1 = (a ^ bb ^ cc) & ~(a & bb & cc);
                p[0][bc] = a & e1;  p[1][bc] = bb & e1;  p[2][bc] = cc & e1;
            }
#pragma unroll
            for (int ri = 0; ri < 3; ++ri)
#pragma unroll
                for (int bc = 0; bc < 3; ++bc) {
                    unsigned keep = ~(p[ri][(bc + 1) % 3] | p[ri][(bc + 2) % 3]);
                    int c0 = (3 * br + ri) * 9 + 3 * bc;
                    m[c0] &= keep;  m[c0 + 1] &= keep;  m[c0 + 2] &= keep;
                }
        }

        // ---- 3. pointing v
#pragma unroll
        for (int bcol = 0; bcol < 3; ++bcol) {
            unsigned seg[3][3];   // [br][ci]
#pragma unroll
            for (int br = 0; br < 3; ++br)
#pragma unroll
                for (int ci = 0; ci < 3; ++ci) {
                    int c0 = (3 * br) * 9 + 3 * bcol + ci;
                    seg[br][ci] = m[c0] | m[c0 + 9] | m[c0 + 18];
                }
            unsigned p[3][3];
#pragma unroll
            for (int br = 0; br < 3; ++br) {
                unsigned a = seg[br][0], bb = seg[br][1], cc = seg[br][2];
                unsigned e1 = (a ^ bb ^ cc) & ~(a & bb & cc);
                p[br][0] = a & e1;  p[br][1] = bb & e1;  p[br][2] = cc & e1;
            }
#pragma unroll
            for (int br = 0; br < 3; ++br)
#pragma unroll
                for (int ci = 0; ci < 3; ++ci) {
                    unsigned keep = ~(p[(br + 1) % 3][ci] | p[(br + 2) % 3][ci]);
                    int c0 = (3 * br) * 9 + 3 * bcol + ci;
                    m[c0] &= keep;  m[c0 + 9] &= keep;  m[c0 + 18] &= keep;
                }
        }

        // ---- 4/5/6. hidden singles: rows, cols, boxes
        UNIQUE_LINE(ROW_IDX)
        UNIQUE_LINE(COL_IDX)
        UNIQUE_LINE(BOX_IDX)

        // ---- 7/8/9. naked pairs: v, v, box (reference's exact sequence)
        DOUBLES_LINE(COL_IDX)
        DOUBLES_LINE(COL_IDX)
        DOUBLES_LINE(BOX_IDX)
    }

    // write back packed result + solved flag
    bool solved = true;
#pragma unroll
    for (int i = 0; i < CELLS; ++i) {
        g_pack[b * CELLS + i] = m[i];
        solved = solved && (__popc(m[i]) == 1);
    }
    if (tail_mode == 1) {
        out_tail[b] = solved ? 1.0f : 0.0f;                 // float tail
    } else if (tail_mode == 2) {
        ((unsigned char*)out_tail)[b] = solved ? 1 : 0;     // bool-byte tail
    }
}

// ---------------------------------------------------------------------------
extern "C" void kernel_launch(void* const* d_in, const int* in_sizes, int n_in,
                              void* d_out, int out_size)
{
    const float* in = (const float*)d_in[0];
    float* out = (float*)d_out;

    int B = in_sizes[0] / 729;
    if (B > MAX_B) B = MAX_B;

    int tail_mode = 0;
    float* tail_ptr = out + (size_t)B * 729;
    if (out_size >= B * 729 + B) {
        tail_mode = 1;                                   // float-encoded bools
    } else if (out_size >= B * 729 + (B + 3) / 4) {
        tail_mode = 2;                                   // raw bool bytes
    }

    {
        int total = B * CELLS;
        int threads = 256;
        pack_kernel<<<(total + threads - 1) / threads, threads>>>(in, B);
    }
    {
        // 147 blocks of 224 threads: one CTA per SM, max 224 puzzles/SM
        // (ideal 221.4) instead of the 256/SM hot spot of the 256x128 grid.
        int blocks = (B + SOLVE_TPB - 1) / SOLVE_TPB;
        solve_kernel<<<blocks, SOLVE_TPB>>>(tail_ptr, B, tail_mode);
    }
    {
        int total = B * 729;
        int threads = 256;
        unpack_kernel<<<(total + threads - 1) / threads, threads>>>(out, B);
    }
}

// round 8
// speedup vs baseline: 1.0590x; 1.0590x over previous
#include <cuda_runtime.h>
#include <cuda_bf16.h>
#include <cstdint>

// ---------------------------------------------------------------------------
// SudokuPasses: 4 passes of {filter(box), pointing(h), pointing(v),
// unique(h), unique(v), unique(box), doubles(v), doubles(v), doubles(box)}
// over B=32768 puzzles of (9 digits, 9 rows, 9 cols) {0,1} float masks.
//
// pack floats -> 81 x 9-bit cell masks, solve in registers (1 thread/puzzle),
// unpack to float.
// R7: revert R6 grid experiment (SMSP-level critical path unchanged by it);
//     doubles rewritten to drop the v[9] shadow copy -- writeback reads m[]
//     in place and only un-flagged cells are modified. Less live state, fewer
//     ops; solver is latency/register-bound, not alu-throughput-bound.
// ---------------------------------------------------------------------------

#define MAX_B 32768
#define CELLS 81

__device__ unsigned int g_pack[MAX_B * CELLS];

// ---------------------------------------------------------------------------
__global__ void pack_kernel(const float* __restrict__ in, int B)
{
    int idx = blockIdx.x * blockDim.x + threadIdx.x;
    if (idx >= B * CELLS) return;
    int b    = idx / CELLS;
    int cell = idx % CELLS;
    const float* p = in + (size_t)b * 729 + cell;
    unsigned m = 0;
#pragma unroll
    for (int d = 0; d < 9; ++d) {
        m |= (__ldcs(p + d * 81) != 0.0f) ? (1u << d) : 0u;
    }
    g_pack[idx] = m;
}

// ---------------------------------------------------------------------------
__global__ void unpack_kernel(float* __restrict__ out, int B)
{
    int idx = blockIdx.x * blockDim.x + threadIdx.x;
    if (idx >= B * 729) return;
    int b    = idx / 729;
    int r3   = idx % 729;
    int d    = r3 / 81;
    int cell = r3 % 81;
    unsigned m = g_pack[b * CELLS + cell];
    __stcs(out + idx, (float)((m >> d) & 1u));
}

// ---------------------------------------------------------------------------
#define ROW_IDX(l, k)  ((l) * 9 + (k))
#define COL_IDX(l, k)  ((k) * 9 + (l))
#define BOX_IDX(l, k)  ((((l) / 3) * 3 + ((k) / 3)) * 9 + ((l) % 3) * 3 + ((k) % 3))

// Hidden single: per-digit-bit count across the 9 cells of a line.
// count==1  <=>  parity set AND no carry ever generated.
#define UNIQUE_LINE(IDX)                                                      \
    _Pragma("unroll")                                                         \
    for (int l = 0; l < 9; ++l) {                                             \
        unsigned ones = 0, more = 0;                                          \
        _Pragma("unroll")                                                     \
        for (int k = 0; k < 9; ++k) {                                         \
            unsigned x = m[IDX(l, k)];                                        \
            more |= ones & x;                                                 \
            ones ^= x;                                                        \
        }                                                                     \
        unsigned e1 = ones & ~more;                                           \
        _Pragma("unroll")                                                     \
        for (int k = 0; k < 9; ++k) {                                         \
            unsigned v = m[IDX(l, k)];                                        \
            unsigned h = v & e1;                                              \
            m[IDX(l, k)] = h ? h : v;                                         \
        }                                                                     \
    }

// Naked pair: dot==2 between 2-candidate cells <=> identical patterns.
// Flagged (pair) cells keep their mask unchanged; all other cells lose the
// union of pair digits. Writeback reads m[] in place -- no shadow copy.
#define DOUBLES_LINE(IDX)                                                     \
    _Pragma("unroll")                                                         \
    for (int l = 0; l < 9; ++l) {                                             \
        unsigned pm[9];                                                       \
        _Pragma("unroll")                                                     \
        for (int k = 0; k < 9; ++k) {                                         \
            unsigned vv = m[IDX(l, k)];                                       \
            pm[k] = (__popc(vv) == 2) ? vv : 0u;                              \
        }                                                                     \
        unsigned flag = 0, pd = 0;                                            \
        _Pragma("unroll")                                                     \
        for (int c = 0; c < 9; ++c) {                                         \
            if (pm[c] != 0u) {                                                \
                _Pragma("unroll")                                             \
                for (int e = c + 1; e < 9; ++e) {                             \
                    if (pm[c] == pm[e]) {                                     \
                        flag |= (1u << c) | (1u << e);                        \
                        pd   |= pm[c];                                        \
                    }                                                         \
                }                                                             \
            }                                                                 \
        }                                                                     \
        unsigned npd = ~pd;                                                   \
        _Pragma("unroll")                                                     \
        for (int k = 0; k < 9; ++k) {                                         \
            if (!((flag >> k) & 1u)) m[IDX(l, k)] &= npd;                     \
        }                                                                     \
    }

__global__ void __launch_bounds__(128)
solve_kernel(float* __restrict__ out_tail, int B, int tail_mode)
{
    int b = blockIdx.x * blockDim.x + threadIdx.x;
    if (b >= B) return;

    unsigned m[CELLS];
#pragma unroll
    for (int i = 0; i < CELLS; ++i) m[i] = g_pack[b * CELLS + i];

#pragma unroll 1
    for (int pass = 0; pass < 4; ++pass) {
        // ---- 1. filter box: solved cell's digit removed from rest of box;
        //         a digit solved twice in a box eliminates both.
#pragma unroll
        for (int bx = 0; bx < 9; ++bx) {
            const int base = (bx / 3) * 27 + (bx % 3) * 3;
            unsigned s[9], seen = 0, seen2 = 0;
#pragma unroll
            for (int k = 0; k < 9; ++k) {
                int idx = base + (k / 3) * 9 + (k % 3);
                unsigned vv = m[idx];
                unsigned sv = (__popc(vv) == 1) ? vv : 0u;
                s[k] = sv;
                seen2 |= seen & sv;
                seen  |= sv;
            }
#pragma unroll
            for (int k = 0; k < 9; ++k) {
                int idx = base + (k / 3) * 9 + (k % 3);
                unsigned other = (seen & ~s[k]) | (seen2 & s[k]);
                m[idx] &= ~other;
            }
        }

        // ---- 2. pointing h
#pragma unroll
        for (int br = 0; br < 3; ++br) {
            unsigned seg[3][3];   // [ri][bc]
#pragma unroll
            for (int ri = 0; ri < 3; ++ri)
#pragma unroll
                for (int bc = 0; bc < 3; ++bc) {
                    int c0 = (3 * br + ri) * 9 + 3 * bc;
                    seg[ri][bc] = m[c0] | m[c0 + 1] | m[c0 + 2];
                }
            unsigned p[3][3];
#pragma unroll
            for (int bc = 0; bc < 3; ++bc) {
                unsigned a = seg[0][bc], bb = seg[1][bc], cc = seg[2][bc];
                unsigned e1 = (a ^ bb ^ cc) & ~(a & bb & cc);
                p[0][bc] = a & e1;  p[1][bc] = bb & e1;  p[2][bc] = cc & e1;
            }
#pragma unroll
            for (int ri = 0; ri < 3; ++ri)
#pragma unroll
                for (int bc = 0; bc < 3; ++bc) {
                    unsigned keep = ~(p[ri][(bc + 1) % 3] | p[ri][(bc + 2) % 3]);
                    int c0 = (3 * br + ri) * 9 + 3 * bc;
                    m[c0] &= keep;  m[c0 + 1] &= keep;  m[c0 + 2] &= keep;
                }
        }

        // ---- 3. pointing v
#pragma unroll
        for (int bcol = 0; bcol < 3; ++bcol) {
            unsigned seg[3][3];   // [br][ci]
#pragma unroll
            for (int br = 0; br < 3; ++br)
#pragma unroll
                for (int ci = 0; ci < 3; ++ci) {
                    int c0 = (3 * br) * 9 + 3 * bcol + ci;
                    seg[br][ci] = m[c0] | m[c0 + 9] | m[c0 + 18];
                }
            unsigned p[3][3];
#pragma unroll
            for (int br = 0; br < 3; ++br) {
                unsigned a = seg[br][0], bb = seg[br][1], cc = seg[br][2];
                unsigned e1 = (a ^ bb ^ cc) & ~(a & bb & cc);
                p[br][0] = a & e1;  p[br][1] = bb & e1;  p[br][2] = cc & e1;
            }
#pragma unroll
            for (int br = 0; br < 3; ++br)
#pragma unroll
                for (int ci = 0; ci < 3; ++ci) {
                    unsigned keep = ~(p[(br + 1) % 3][ci] | p[(br + 2) % 3][ci]);
                    int c0 = (3 * br) * 9 + 3 * bcol + ci;
                    m[c0] &= keep;  m[c0 + 9] &= keep;  m[c0 + 18] &= keep;
                }
        }

        // ---- 4/5/6. hidden singles: rows, cols, boxes
        UNIQUE_LINE(ROW_IDX)
        UNIQUE_LINE(COL_IDX)
        UNIQUE_LINE(BOX_IDX)

        // ---- 7/8/9. naked pairs: v, v, box (reference's exact sequence)
        DOUBLES_LINE(COL_IDX)
        DOUBLES_LINE(COL_IDX)
        DOUBLES_LINE(BOX_IDX)
    }

    // write back packed result + solved flag
    bool solved = true;
#pragma unroll
    for (int i = 0; i < CELLS; ++i) {
        g_pack[b * CELLS + i] = m[i];
        solved = solved && (__popc(m[i]) == 1);
    }
    if (tail_mode == 1) {
        out_tail[b] = solved ? 1.0f : 0.0f;                 // float tail
    } else if (tail_mode == 2) {
        ((unsigned char*)out_tail)[b] = solved ? 1 : 0;     // bool-byte tail
    }
}

// ---------------------------------------------------------------------------
extern "C" void kernel_launch(void* const* d_in, const int* in_sizes, int n_in,
                              void* d_out, int out_size)
{
    const float* in = (const float*)d_in[0];
    float* out = (float*)d_out;

    int B = in_sizes[0] / 729;
    if (B > MAX_B) B = MAX_B;

    int tail_mode = 0;
    float* tail_ptr = out + (size_t)B * 729;
    if (out_size >= B * 729 + B) {
        tail_mode = 1;                                   // float-encoded bools
    } else if (out_size >= B * 729 + (B + 3) / 4) {
        tail_mode = 2;                                   // raw bool bytes
    }

    {
        int total = B * CELLS;
        int threads = 256;
        pack_kernel<<<(total + threads - 1) / threads, threads>>>(in, B);
    }
    {
        int threads = 128;
        solve_kernel<<<(B + threads - 1) / threads, threads>>>(tail_ptr, B, tail_mode);
    }
    {
        int total = B * 729;
        int threads = 256;
        unpack_kernel<<<(total + threads - 1) / threads, threads>>>(out, B);
    }
}

// round 9
// speedup vs baseline: 1.1485x; 1.0844x over previous
#include <cuda_runtime.h>
#include <cuda_bf16.h>
#include <cstdint>

// ---------------------------------------------------------------------------
// SudokuPasses: 4 passes of {filter(box), pointing(h), pointing(v),
// unique(h), unique(v), unique(box), doubles(v), doubles(v), doubles(box)}
// over B=32768 puzzles of (9 digits, 9 rows, 9 cols) {0,1} float masks.
//
// pack floats -> 81 x 9-bit cell masks, solve in registers (1 thread/puzzle),
// unpack to float.
// R8: back to R5 structure (best: 144.1us). Doubles guard folded into a
//     per-cell sentinel (no nz branch). Trailing no-op launch aligns ncu's
//     "-s 5" onto solve_kernel for the next round's diagnosis.
// ---------------------------------------------------------------------------

#define MAX_B 32768
#define CELLS 81

__device__ unsigned int g_pack[MAX_B * CELLS];

// ---------------------------------------------------------------------------
__global__ void pack_kernel(const float* __restrict__ in, int B)
{
    int idx = blockIdx.x * blockDim.x + threadIdx.x;
    if (idx >= B * CELLS) return;
    int b    = idx / CELLS;
    int cell = idx % CELLS;
    const float* p = in + (size_t)b * 729 + cell;
    unsigned m = 0;
#pragma unroll
    for (int d = 0; d < 9; ++d) {
        m |= (__ldcs(p + d * 81) != 0.0f) ? (1u << d) : 0u;
    }
    g_pack[idx] = m;
}

// ---------------------------------------------------------------------------
__global__ void unpack_kernel(float* __restrict__ out, int B)
{
    int idx = blockIdx.x * blockDim.x + threadIdx.x;
    if (idx >= B * 729) return;
    int b    = idx / 729;
    int r3   = idx % 729;
    int d    = r3 / 81;
    int cell = r3 % 81;
    unsigned m = g_pack[b * CELLS + cell];
    __stcs(out + idx, (float)((m >> d) & 1u));
}

// no-op: shifts ncu's launch-index window so "-s 5" lands on solve_kernel.
__global__ void noop_kernel() {}

// ---------------------------------------------------------------------------
#define ROW_IDX(l, k)  ((l) * 9 + (k))
#define COL_IDX(l, k)  ((k) * 9 + (l))
#define BOX_IDX(l, k)  ((((l) / 3) * 3 + ((k) / 3)) * 9 + ((l) % 3) * 3 + ((k) % 3))

// Hidden single: per-digit-bit count across the 9 cells of a line.
// count==1  <=>  parity set AND no carry ever generated.
#define UNIQUE_LINE(IDX)                                                      \
    _Pragma("unroll")                                                         \
    for (int l = 0; l < 9; ++l) {                                             \
        unsigned ones = 0, more = 0;                                          \
        _Pragma("unroll")                                                     \
        for (int k = 0; k < 9; ++k) {                                         \
            unsigned x = m[IDX(l, k)];                                        \
            more |= ones & x;                                                 \
            ones ^= x;                                                        \
        }                                                                     \
        unsigned e1 = ones & ~more;                                           \
        _Pragma("unroll")                                                     \
        for (int k = 0; k < 9; ++k) {                                         \
            unsigned v = m[IDX(l, k)];                                        \
            unsigned h = v & e1;                                              \
            m[IDX(l, k)] = h ? h : v;                                         \
        }                                                                     \
    }

// Naked pair: identical 2-candidate patterns (sentinel-guarded equality:
// qm is the pattern for 2-candidate cells, else a per-cell-unique sentinel
// above bit 9 -> sentinels never match anything). Pair cells keep their
// mask; all other cells lose the union of pair digits.
#define DOUBLES_LINE(IDX)                                                     \
    _Pragma("unroll")                                                         \
    for (int l = 0; l < 9; ++l) {                                             \
        unsigned v[9], qm[9];                                                 \
        _Pragma("unroll")                                                     \
        for (int k = 0; k < 9; ++k) {                                         \
            v[k]  = m[IDX(l, k)];                                             \
            qm[k] = (__popc(v[k]) == 2) ? v[k] : (0x400u << k);               \
        }                                                                     \
        unsigned flag = 0, pd = 0;                                            \
        _Pragma("unroll")                                                     \
        for (int c = 0; c < 9; ++c) {                                         \
            _Pragma("unroll")                                                 \
            for (int e = c + 1; e < 9; ++e) {                                 \
                if (qm[c] == qm[e]) {                                         \
                    flag |= (1u << c) | (1u << e);                            \
                    pd   |= qm[c];                                            \
                }                                                             \
            }                                                                 \
        }                                                                     \
        unsigned npd = ~pd;                                                   \
        _Pragma("unroll")                                                     \
        for (int k = 0; k < 9; ++k) {                                         \
            m[IDX(l, k)] = ((flag >> k) & 1u) ? v[k] : (v[k] & npd);          \
        }                                                                     \
    }

__global__ void __launch_bounds__(128)
solve_kernel(float* __restrict__ out_tail, int B, int tail_mode)
{
    int b = blockIdx.x * blockDim.x + threadIdx.x;
    if (b >= B) return;

    unsigned m[CELLS];
#pragma unroll
    for (int i = 0; i < CELLS; ++i) m[i] = g_pack[b * CELLS + i];

#pragma unroll 1
    for (int pass = 0; pass < 4; ++pass) {
        // ---- 1. filter box: solved cell's digit removed from rest of box;
        //         a digit solved twice in a box eliminates both.
#pragma unroll
        for (int bx = 0; bx < 9; ++bx) {
            const int base = (bx / 3) * 27 + (bx % 3) * 3;
            unsigned s[9], seen = 0, seen2 = 0;
#pragma unroll
            for (int k = 0; k < 9; ++k) {
                int idx = base + (k / 3) * 9 + (k % 3);
                unsigned vv = m[idx];
                unsigned sv = (__popc(vv) == 1) ? vv : 0u;
                s[k] = sv;
                seen2 |= seen & sv;
                seen  |= sv;
            }
#pragma unroll
            for (int k = 0; k < 9; ++k) {
                int idx = base + (k / 3) * 9 + (k % 3);
                unsigned other = (seen & ~s[k]) | (seen2 & s[k]);
                m[idx] &= ~other;
            }
        }

        // ---- 2. pointing h
#pragma unroll
        for (int br = 0; br < 3; ++br) {
            unsigned seg[3][3];   // [ri][bc]
#pragma unroll
            for (int ri = 0; ri < 3; ++ri)
#pragma unroll
                for (int bc = 0; bc < 3; ++bc) {
                    int c0 = (3 * br + ri) * 9 + 3 * bc;
                    seg[ri][bc] = m[c0] | m[c0 + 1] | m[c0 + 2];
                }
            unsigned p[3][3];
#pragma unroll
            for (int bc = 0; bc < 3; ++bc) {
                unsigned a = seg[0][bc], bb = seg[1][bc], cc = seg[2][bc];
                unsigned e1 = (a ^ bb ^ cc) & ~(a & bb & cc);
                p[0][bc] = a & e1;  p[1][bc] = bb & e1;  p[2][bc] = cc & e1;
            }
#pragma unroll
            for (int ri = 0; ri < 3; ++ri)
#pragma unroll
                for (int bc = 0; bc < 3; ++bc) {
                    unsigned keep = ~(p[ri][(bc + 1) % 3] | p[ri][(bc + 2) % 3]);
                    int c0 = (3 * br + ri) * 9 + 3 * bc;
                    m[c0] &= keep;  m[c0 + 1] &= keep;  m[c0 + 2] &= keep;
                }
        }

        // ---- 3. pointing v
#pragma unroll
        for (int bcol = 0; bcol < 3; ++bcol) {
            unsigned seg[3][3];   // [br][ci]
#pragma unroll
            for (int br = 0; br < 3; ++br)
#pragma unroll
                for (int ci = 0; ci < 3; ++ci) {
                    int c0 = (3 * br) * 9 + 3 * bcol + ci;
                    seg[br][ci] = m[c0] | m[c0 + 9] | m[c0 + 18];
                }
            unsigned p[3][3];
#pragma unroll
            for (int br = 0; br < 3; ++br) {
                unsigned a = seg[br][0], bb = seg[br][1], cc = seg[br][2];
                unsigned e1 = (a ^ bb ^ cc) & ~(a & bb & cc);
                p[br][0] = a & e1;  p[br][1] = bb & e1;  p[br][2] = cc & e1;
            }
#pragma unroll
            for (int br = 0; br < 3; ++br)
#pragma unroll
                for (int ci = 0; ci < 3; ++ci) {
                    unsigned keep = ~(p[(br + 1) % 3][ci] | p[(br + 2) % 3][ci]);
                    int c0 = (3 * br) * 9 + 3 * bcol + ci;
                    m[c0] &= keep;  m[c0 + 9] &= keep;  m[c0 + 18] &= keep;
                }
        }

        // ---- 4/5/6. hidden singles: rows, cols, boxes
        UNIQUE_LINE(ROW_IDX)
        UNIQUE_LINE(COL_IDX)
        UNIQUE_LINE(BOX_IDX)

        // ---- 7/8/9. naked pairs: v, v, box (reference's exact sequence)
        DOUBLES_LINE(COL_IDX)
        DOUBLES_LINE(COL_IDX)
        DOUBLES_LINE(BOX_IDX)
    }

    // write back packed result + solved flag
    bool solved = true;
#pragma unroll
    for (int i = 0; i < CELLS; ++i) {
        g_pack[b * CELLS + i] = m[i];
        solved = solved && (__popc(m[i]) == 1);
    }
    if (tail_mode == 1) {
        out_tail[b] = solved ? 1.0f : 0.0f;                 // float tail
    } else if (tail_mode == 2) {
        ((unsigned char*)out_tail)[b] = solved ? 1 : 0;     // bool-byte tail
    }
}

// ---------------------------------------------------------------------------
extern "C" void kernel_launch(void* const* d_in, const int* in_sizes, int n_in,
                              void* d_out, int out_size)
{
    const float* in = (const float*)d_in[0];
    float* out = (float*)d_out;

    int B = in_sizes[0] / 729;
    if (B > MAX_B) B = MAX_B;

    int tail_mode = 0;
    float* tail_ptr = out + (size_t)B * 729;
    if (out_size >= B * 729 + B) {
        tail_mode = 1;                                   // float-encoded bools
    } else if (out_size >= B * 729 + (B + 3) / 4) {
        tail_mode = 2;                                   // raw bool bytes
    }

    {
        int total = B * CELLS;
        int threads = 256;
        pack_kernel<<<(total + threads - 1) / threads, threads>>>(in, B);
    }
    {
        int threads = 128;
        solve_kernel<<<(B + threads - 1) / threads, threads>>>(tail_ptr, B, tail_mode);
    }
    {
        int total = B * 729;
        int threads = 256;
        unpack_kernel<<<(total + threads - 1) / threads, threads>>>(out, B);
    }
    // 4 launches per call -> ncu "-s 5 -c 1" captures launch #5 = the
    // second call's solve_kernel (indices: pack0,solve1,unpack2,noop3,
    // pack4,SOLVE5). Diagnostic only; ~1us cost.
    noop_kernel<<<1, 1>>>();
}